// round 2
// baseline (speedup 1.0000x reference)
#include <cuda_runtime.h>
#include <cfloat>
#include <math.h>

// Problem constants (fixed by the benchmark)
#define BB   2
#define CC   2
#define NN   1024
#define HH   8
#define FF   64
#define FIN2 (HH*FF)          // 512
#define NSL  (BB*CC*HH)       // 32 attention slices

// ---------------- scratch (device globals: allocation-free) ----------------
__device__ unsigned int g_mask[BB*NN*(NN/32)];            // packed valid-edge bits (incl self loops)
__device__ float g_hp[(size_t)NSL*NN*FF];                 // h_prime for current layer
__device__ float g_s [NSL*NN];                            // src scores
__device__ float g_d [NSL*NN];                            // dst scores
__device__ float g_x1[(size_t)BB*CC*NN*FIN2];             // layer-1 output (elu, head-flattened)
__device__ float g_o2[(size_t)NSL*NN*FF];                 // layer-2 attention output (pre head-mean)

// ---------------- f32x2 helpers ----------------
union f2u  { float2 f; unsigned long long u; };
union f4u  { float4 f; unsigned long long u[2]; };

__device__ __forceinline__ unsigned long long pack2(float a, float b){
    unsigned long long r;
    asm("mov.b64 %0, {%1,%2};" : "=l"(r) : "f"(a), "f"(b));
    return r;
}
__device__ __forceinline__ void ffma2(unsigned long long &d, unsigned long long a, unsigned long long b){
    asm("fma.rn.f32x2 %0, %1, %2, %0;" : "+l"(d) : "l"(a), "l"(b));
}
__device__ __forceinline__ void fmul2(unsigned long long &d, unsigned long long a){
    asm("mul.rn.f32x2 %0, %0, %1;" : "+l"(d) : "l"(a));
}

// ---------------- kernel 1: pack adjacency (+self loops) into bitmask ----------------
__global__ void pack_mask_kernel(const int* __restrict__ adj){
    int n = blockIdx.x, b = blockIdx.y, m = threadIdx.x;   // block of 1024 threads
    bool valid = (adj[((size_t)b*NN + n)*NN + m] != 0) || (m == n);
    unsigned bits = __ballot_sync(0xffffffffu, valid);
    if ((m & 31) == 0) g_mask[((size_t)b*NN + n)*32 + (m >> 5)] = bits;
}

// ---------------- kernel 2: h_prime = x @ w  (+ tanh -> s,d scores) ----------------
// grid: (NSL, NN/64), block 256 (8 warps x 8 rows). K-chunked by 64.
template<int FIN, bool FROMX1>
__global__ __launch_bounds__(256) void gemm_sd_kernel(
    const float* __restrict__ xin, const float* __restrict__ w,
    const float* __restrict__ a_src, const float* __restrict__ a_dst)
{
    __shared__ float xs[64*64];
    __shared__ float ws[64*64];
    __shared__ float as_s[64], ad_s[64];

    const int sl = blockIdx.x, n0 = blockIdx.y*64;
    const int b = sl/(CC*HH), c = (sl/HH)%CC, h = sl%HH;
    const int tid = threadIdx.x, lane = tid & 31, warp = tid >> 5;

    const float* x = FROMX1 ? (const float*)g_x1 : xin;
    const float* xbase = x + ((size_t)(b*CC + c)*NN + n0)*FIN;
    const float* wbase = w + (size_t)(c*HH + h)*FIN*FF;

    if (tid < 64){
        int ch = (c*HH + h)*FF;
        as_s[tid] = a_src[ch + tid];
        ad_s[tid] = a_dst[ch + tid];
    }

    float acc0[8], acc1[8];
    #pragma unroll
    for (int r = 0; r < 8; r++){ acc0[r] = 0.f; acc1[r] = 0.f; }

    const int row4 = tid >> 6, col = tid & 63;
    for (int kc = 0; kc < FIN/64; kc++){
        #pragma unroll
        for (int rr = 0; rr < 16; rr++)
            xs[(4*rr + row4)*64 + col] = xbase[(size_t)(4*rr + row4)*FIN + kc*64 + col];
        const float* wsrc = wbase + (size_t)kc*64*FF;    // contiguous 4096 floats
        #pragma unroll
        for (int q = 0; q < 16; q++) ws[tid + 256*q] = wsrc[tid + 256*q];
        __syncthreads();

        #pragma unroll 4
        for (int i = 0; i < 64; i++){
            float w0 = ws[i*64 + lane];
            float w1 = ws[i*64 + lane + 32];
            #pragma unroll
            for (int r = 0; r < 8; r++){
                float xv = xs[(warp*8 + r)*64 + i];       // smem broadcast
                acc0[r] = fmaf(xv, w0, acc0[r]);
                acc1[r] = fmaf(xv, w1, acc1[r]);
            }
        }
        __syncthreads();
    }

    #pragma unroll
    for (int r = 0; r < 8; r++){
        const int n = n0 + warp*8 + r;
        const size_t hb = ((size_t)sl*NN + n)*FF;
        g_hp[hb + lane]      = acc0[r];
        g_hp[hb + lane + 32] = acc1[r];
        float t0 = tanhf(acc0[r]), t1 = tanhf(acc1[r]);
        float sp = t0*as_s[lane] + t1*as_s[lane + 32];
        float dp = t0*ad_s[lane] + t1*ad_s[lane + 32];
        #pragma unroll
        for (int o = 16; o; o >>= 1){
            sp += __shfl_xor_sync(0xffffffffu, sp, o);
            dp += __shfl_xor_sync(0xffffffffu, dp, o);
        }
        if (lane == 0){ g_s[sl*NN + n] = sp; g_d[sl*NN + n] = dp; }
    }
}

// ---------------- kernel 3: masked-softmax attention + P @ h_prime ----------------
// grid (NSL, NN/64), block 256. 64 rows/block, m-tile MT=64 (online softmax).
// Score phase: warp w owns rows 8w..8w+7. Accumulate phase: thread (tx,ty) owns
// rows 4ty..4ty+3 x features 4tx..4tx+3 — a register-tiled GEMM with fma.rn.f32x2.
template<bool LAYER1>
__global__ __launch_bounds__(256) void attn_kernel(){
    const int MT = 64;
    const int EP = MT + 1;                 // padded e row stride (bank-conflict free reads)
    __shared__ float hp_s[MT*FF];          // [mm][f]    16 KB
    __shared__ float e_s[64*EP];           // [row][mm]  16.25 KB
    __shared__ float scale_s[64];
    __shared__ float l_s[64];

    const int sl = blockIdx.x, n0 = blockIdx.y*64;
    const int b = sl/(CC*HH), c = (sl/HH)%CC, h = sl%HH;
    const int tid = threadIdx.x, lane = tid & 31, warp = tid >> 5;
    const int tx = tid & 15, ty = tid >> 4;

    // per-warp online-softmax state for rows 8*warp + r
    float s_n[8], run_m[8], lsum[8];
    #pragma unroll
    for (int r = 0; r < 8; r++){
        s_n[r]   = g_s[sl*NN + n0 + warp*8 + r];
        run_m[r] = -FLT_MAX;
        lsum[r]  = 0.f;
    }

    f2u acc[8];                            // 4 rows x 4 f (as 2x f32x2 per row)
    #pragma unroll
    for (int j = 0; j < 8; j++) acc[j].u = 0ull;

    const float*    dbase = g_d + sl*NN;
    const unsigned* mbase = g_mask + (size_t)b*NN*32;

    for (int m0 = 0; m0 < NN; m0 += MT){
        __syncthreads();                   // prev accumulate done with hp_s/e_s/scale_s

        // stage h_prime tile (contiguous 4096 floats)
        const float4* hsrc = (const float4*)(g_hp + ((size_t)sl*NN + m0)*FF);
        #pragma unroll
        for (int q = 0; q < 4; q++) ((float4*)hp_s)[tid + 256*q] = hsrc[tid + 256*q];

        const float d0 = dbase[m0 + lane];
        const float d1 = dbase[m0 + lane + 32];
        const int w0i = m0 >> 5;

        #pragma unroll
        for (int r = 0; r < 8; r++){
            const int row = warp*8 + r;
            const unsigned* mrow = mbase + (size_t)(n0 + row)*32 + w0i;
            unsigned mw = (lane < 2) ? mrow[lane] : 0u;
            unsigned mwa = __shfl_sync(0xffffffffu, mw, 0);
            unsigned mwb = __shfl_sync(0xffffffffu, mw, 1);
            bool v0 = (mwa >> lane) & 1u;
            bool v1 = (mwb >> lane) & 1u;

            float r0 = s_n[r] + d0; r0 = (r0 >= 0.f) ? r0 : 0.2f*r0;   // leaky_relu(0.2)
            float r1 = s_n[r] + d1; r1 = (r1 >= 0.f) ? r1 : 0.2f*r1;

            float tm = fmaxf(v0 ? r0 : -FLT_MAX, v1 ? r1 : -FLT_MAX);
            #pragma unroll
            for (int o = 16; o; o >>= 1) tm = fmaxf(tm, __shfl_xor_sync(0xffffffffu, tm, o));

            float nm = fmaxf(run_m[r], tm);
            float sc = __expf(run_m[r] - nm);          // exp(0)=1 if tile fully masked
            run_m[r] = nm;
            float e0 = v0 ? __expf(r0 - nm) : 0.f;     // masked -> exactly 0 (matches ref fp32)
            float e1 = v1 ? __expf(r1 - nm) : 0.f;
            float es = e0 + e1;
            #pragma unroll
            for (int o = 16; o; o >>= 1) es += __shfl_xor_sync(0xffffffffu, es, o);
            lsum[r] = lsum[r]*sc + es;

            e_s[row*EP + lane]      = e0;
            e_s[row*EP + lane + 32] = e1;
            if (lane == 0) scale_s[row] = sc;
        }
        __syncthreads();

        // rescale accumulators, then P @ h_prime (register-tiled, f32x2)
        #pragma unroll
        for (int j = 0; j < 4; j++){
            float sc = scale_s[4*ty + j];
            unsigned long long scp = pack2(sc, sc);
            fmul2(acc[2*j].u,     scp);
            fmul2(acc[2*j + 1].u, scp);
        }
        #pragma unroll 2
        for (int k = 0; k < MT; k++){
            f4u h4; h4.f = *(const float4*)&hp_s[k*FF + 4*tx];
            #pragma unroll
            for (int j = 0; j < 4; j++){
                float e = e_s[(4*ty + j)*EP + k];
                unsigned long long ee = pack2(e, e);
                ffma2(acc[2*j].u,     h4.u[0], ee);
                ffma2(acc[2*j + 1].u, h4.u[1], ee);
            }
        }
    }

    if (lane == 0){
        #pragma unroll
        for (int r = 0; r < 8; r++) l_s[warp*8 + r] = lsum[r];
    }
    __syncthreads();

    #pragma unroll
    for (int j = 0; j < 4; j++){
        const int row = 4*ty + j;
        const float inv = 1.f / l_s[row];
        float o0 = acc[2*j].f.x     * inv;
        float o1 = acc[2*j].f.y     * inv;
        float o2 = acc[2*j + 1].f.x * inv;
        float o3 = acc[2*j + 1].f.y * inv;
        const int n = n0 + row;
        if (LAYER1){
            float4 v;
            v.x = (o0 > 0.f) ? o0 : expm1f(o0);        // elu
            v.y = (o1 > 0.f) ? o1 : expm1f(o1);
            v.z = (o2 > 0.f) ? o2 : expm1f(o2);
            v.w = (o3 > 0.f) ? o3 : expm1f(o3);
            *(float4*)&g_x1[((size_t)(b*CC + c)*NN + n)*FIN2 + h*FF + 4*tx] = v;
        } else {
            float4 v = make_float4(o0, o1, o2, o3);
            *(float4*)&g_o2[((size_t)sl*NN + n)*FF + 4*tx] = v;
        }
    }
}

// ---------------- kernel 4: mean over heads ----------------
__global__ void reduce_mean_kernel(float* __restrict__ out){
    int idx = blockIdx.x*blockDim.x + threadIdx.x;          // B*C*N*F = 262144
    int f  = idx & 63;
    int nn = (idx >> 6) & (NN - 1);
    int bc = idx >> 16;                                     // NN*FF = 65536
    float sum = 0.f;
    #pragma unroll
    for (int h = 0; h < HH; h++)
        sum += g_o2[(((size_t)bc*HH + h)*NN + nn)*FF + f];
    out[idx] = sum * (1.f / HH);
}

// ---------------- launch ----------------
extern "C" void kernel_launch(void* const* d_in, const int* in_sizes, int n_in,
                              void* d_out, int out_size)
{
    const float* x   = (const float*)d_in[0];
    const int*   adj = (const int*)  d_in[1];
    const float* w1  = (const float*)d_in[2];
    const float* as1 = (const float*)d_in[3];
    const float* ad1 = (const float*)d_in[4];
    const float* w2  = (const float*)d_in[5];
    const float* as2 = (const float*)d_in[6];
    const float* ad2 = (const float*)d_in[7];
    float* out = (float*)d_out;

    pack_mask_kernel<<<dim3(NN, BB), 1024>>>(adj);

    gemm_sd_kernel<64,  false><<<dim3(NSL, NN/64), 256>>>(x, w1, as1, ad1);
    attn_kernel<true ><<<dim3(NSL, NN/64), 256>>>();

    gemm_sd_kernel<FIN2, true><<<dim3(NSL, NN/64), 256>>>(nullptr, w2, as2, ad2);
    attn_kernel<false><<<dim3(NSL, NN/64), 256>>>();

    reduce_mean_kernel<<<(BB*CC*NN*FF)/256, 256>>>(out);
}